// round 16
// baseline (speedup 1.0000x reference)
#include <cuda_runtime.h>
#include <cuda_bf16.h>
#include <math.h>
#include <stdint.h>

#define HEADS 6
#define NTOK  64
#define DIM   192
#define MAXB  4096

// ---------------- device scratch ----------------
__device__ float g_bias16[HEADS * NTOK * NTOK];
__device__ float g_bm[64 * HEADS * NTOK * NTOK];   // mask + bias16 combined
// normalized (scale folded) q, k and v, bf16 hi/lo split, [b][h][n][32]
__device__ __align__(16) __nv_bfloat16 g_qh[(size_t)MAXB * HEADS * 2048];
__device__ __align__(16) __nv_bfloat16 g_ql[(size_t)MAXB * HEADS * 2048];
__device__ __align__(16) __nv_bfloat16 g_kh[(size_t)MAXB * HEADS * 2048];
__device__ __align__(16) __nv_bfloat16 g_kl[(size_t)MAXB * HEADS * 2048];
__device__ __align__(16) __nv_bfloat16 g_vh[(size_t)MAXB * HEADS * 2048];
__device__ __align__(16) __nv_bfloat16 g_vl[(size_t)MAXB * HEADS * 2048];
// attention output, bf16 hi/lo, [b][n][192]
__device__ __align__(16) __nv_bfloat16 g_oh[(size_t)MAXB * NTOK * DIM];
__device__ __align__(16) __nv_bfloat16 g_ol[(size_t)MAXB * NTOK * DIM];
// weights bf16 hi/lo
__device__ __align__(16) __nv_bfloat16 gwq_hi[576 * 192];
__device__ __align__(16) __nv_bfloat16 gwq_lo[576 * 192];
__device__ __align__(16) __nv_bfloat16 gwp_hi[192 * 192];
__device__ __align__(16) __nv_bfloat16 gwp_lo[192 * 192];

// ---------------- arch-generic PTX helpers ----------------
__device__ __forceinline__ uint32_t smem_u32(const void* p) {
    uint32_t a;
    asm("{ .reg .u64 t; cvta.to.shared.u64 t, %1; cvt.u32.u64 %0, t; }" : "=r"(a) : "l"(p));
    return a;
}
__device__ __forceinline__ void cp_async16(uint32_t saddr, const void* gptr) {
    asm volatile("cp.async.cg.shared.global [%0], [%1], 16;" :: "r"(saddr), "l"(gptr)
                 : "memory");
}
__device__ __forceinline__ void cp_commit() {
    asm volatile("cp.async.commit_group;" ::: "memory");
}
__device__ __forceinline__ void cp_wait0() {
    asm volatile("cp.async.wait_group 0;" ::: "memory");
}
__device__ __forceinline__ void ldsm4(uint32_t* r, uint32_t addr) {
    asm volatile("ldmatrix.sync.aligned.m8n8.x4.shared.b16 {%0,%1,%2,%3}, [%4];"
                 : "=r"(r[0]), "=r"(r[1]), "=r"(r[2]), "=r"(r[3]) : "r"(addr));
}
__device__ __forceinline__ void ldsm4t(uint32_t* r, uint32_t addr) {
    asm volatile("ldmatrix.sync.aligned.m8n8.x4.trans.shared.b16 {%0,%1,%2,%3}, [%4];"
                 : "=r"(r[0]), "=r"(r[1]), "=r"(r[2]), "=r"(r[3]) : "r"(addr));
}
__device__ __forceinline__ void mma16816(float* c, const uint32_t* a, const uint32_t* b) {
    asm volatile(
        "mma.sync.aligned.m16n8k16.row.col.f32.bf16.bf16.f32 "
        "{%0,%1,%2,%3}, {%4,%5,%6,%7}, {%8,%9}, {%0,%1,%2,%3};"
        : "+f"(c[0]), "+f"(c[1]), "+f"(c[2]), "+f"(c[3])
        : "r"(a[0]), "r"(a[1]), "r"(a[2]), "r"(a[3]), "r"(b[0]), "r"(b[1]));
}
__device__ __forceinline__ uint32_t pk(__nv_bfloat16 a, __nv_bfloat16 b) {
    __nv_bfloat162 t = __halves2bfloat162(a, b);
    return *(uint32_t*)&t;
}

// ================= GEMM common =================
#define ASTRIDE 400
#define A_HI    0
#define A_LO    51200
#define BBUF(buf)       (102400 + (buf) * 51200)
#define SBIAS   204800
#define SM_DYN  (204800 + 2304)
#define GEMM_THREADS 512

__global__ void prep_w_kernel(const float* __restrict__ qkvw, const float* __restrict__ pw) {
    const int n1 = 576 * 192, n2 = 192 * 192;
    for (int i = blockIdx.x * blockDim.x + threadIdx.x; i < n1 + n2;
         i += gridDim.x * blockDim.x) {
        float v = (i < n1) ? qkvw[i] : pw[i - n1];
        __nv_bfloat16 h = __float2bfloat16(v);
        __nv_bfloat16 l = __float2bfloat16(v - __bfloat162float(h));
        if (i < n1) { gwq_hi[i] = h; gwq_lo[i] = l; }
        else        { gwp_hi[i - n1] = h; gwp_lo[i - n1] = l; }
    }
}

__device__ __forceinline__ void stage_A(char* sm, const float* __restrict__ A, int t) {
    const float4* src = (const float4*)A;
#pragma unroll 4
    for (int i = t; i < 6144; i += GEMM_THREADS) {
        float4 v = src[i];
        int row = i / 48, c4 = (i - row * 48) * 4;
        __nv_bfloat16 hx = __float2bfloat16(v.x), hy = __float2bfloat16(v.y);
        __nv_bfloat16 hz = __float2bfloat16(v.z), hw = __float2bfloat16(v.w);
        __nv_bfloat16 lx = __float2bfloat16(v.x - __bfloat162float(hx));
        __nv_bfloat16 ly = __float2bfloat16(v.y - __bfloat162float(hy));
        __nv_bfloat16 lz = __float2bfloat16(v.z - __bfloat162float(hz));
        __nv_bfloat16 lw = __float2bfloat16(v.w - __bfloat162float(hw));
        uint32_t off = row * ASTRIDE + c4 * 2;
        *(uint2*)(sm + A_HI + off) = make_uint2(pk(hx, hy), pk(hz, hw));
        *(uint2*)(sm + A_LO + off) = make_uint2(pk(lx, ly), pk(lz, lw));
    }
}

__device__ __forceinline__ void stage_B_async(uint32_t smb, int buf,
                                              const __nv_bfloat16* __restrict__ Whi,
                                              const __nv_bfloat16* __restrict__ Wlo,
                                              int J, int t) {
    uint32_t bh = smb + BBUF(buf), bl = bh + 25600;
#pragma unroll
    for (int i = t; i < 1536; i += GEMM_THREADS) {
        int n = i / 24, c = (i - n * 24) * 16;
        uint32_t so = n * ASTRIDE + c;
        cp_async16(bh + so, (const char*)(Whi + (size_t)(J + n) * 192) + c);
        cp_async16(bl + so, (const char*)(Wlo + (size_t)(J + n) * 192) + c);
    }
    cp_commit();
}

// Warp tile 16(M) x 32(N); 16 warps: warp_m = warp&7, warp_n = warp>>3.
// Software-pipelined: fragments for ks+1 are loaded before issuing ks MMAs,
// so LDSM (L1 pipe) and HMMA (tensor pipe) overlap instead of serializing.
__device__ __forceinline__ void mma_chunk16(uint32_t smb, int buf, int warp, int lane,
                                            float acc[4][4]) {
    const int warp_m = warp & 7, warp_n = warp >> 3;
    const uint32_t lrow = lane & 15;
    const uint32_t lcol = (lane >> 4) * 16;
    const uint32_t a_hi = smb + A_HI + (warp_m * 16 + lrow) * ASTRIDE + lcol;
    const uint32_t a_lo = a_hi + (A_LO - A_HI);
    const uint32_t b_hi = smb + BBUF(buf) + (warp_n * 32 + lrow) * ASTRIDE + lcol;
    const uint32_t b_lo = b_hi + 25600;

    uint32_t ah[2][4], al[2][4], bh[2][2][4], bl[2][2][4];
    // preload ks = 0
    ldsm4(ah[0], a_hi);
    ldsm4(al[0], a_lo);
    ldsm4(bh[0][0], b_hi);
    ldsm4(bl[0][0], b_lo);
    ldsm4(bh[0][1], b_hi + 16 * ASTRIDE);
    ldsm4(bl[0][1], b_lo + 16 * ASTRIDE);

#pragma unroll
    for (int ks = 0; ks < 12; ++ks) {
        const int cur = ks & 1, nxt = cur ^ 1;
        if (ks < 11) {
            const uint32_t ko = (ks + 1) * 32;
            ldsm4(ah[nxt], a_hi + ko);
            ldsm4(al[nxt], a_lo + ko);
            ldsm4(bh[nxt][0], b_hi + ko);
            ldsm4(bl[nxt][0], b_lo + ko);
            ldsm4(bh[nxt][1], b_hi + 16 * ASTRIDE + ko);
            ldsm4(bl[nxt][1], b_lo + 16 * ASTRIDE + ko);
        }
#pragma unroll
        for (int nh = 0; nh < 2; ++nh) {
            uint32_t b0h[2] = {bh[cur][nh][0], bh[cur][nh][2]};
            uint32_t b1h[2] = {bh[cur][nh][1], bh[cur][nh][3]};
            uint32_t b0l[2] = {bl[cur][nh][0], bl[cur][nh][2]};
            uint32_t b1l[2] = {bl[cur][nh][1], bl[cur][nh][3]};
            mma16816(acc[nh * 2 + 0], ah[cur], b0h);
            mma16816(acc[nh * 2 + 0], ah[cur], b0l);
            mma16816(acc[nh * 2 + 0], al[cur], b0h);
            mma16816(acc[nh * 2 + 1], ah[cur], b1h);
            mma16816(acc[nh * 2 + 1], ah[cur], b1l);
            mma16816(acc[nh * 2 + 1], al[cur], b1h);
        }
    }
}

// ---------------------------------------------------------------------------
// qkv GEMM + fused normalize/scale/bf16-split epilogue. 512 threads.
// ---------------------------------------------------------------------------
__global__ __launch_bounds__(GEMM_THREADS, 1)
void qkv_mma_kernel(const float* __restrict__ x, const float* __restrict__ qb,
                    const float* __restrict__ vb, const float* __restrict__ ls) {
    extern __shared__ char sm[];
    const uint32_t smb = smem_u32(sm);
    const int t = threadIdx.x, warp = t >> 5, lane = t & 31;

    float* sbias = (float*)(sm + SBIAS);
    for (int i = t; i < 576; i += GEMM_THREADS) {
        int s = i / 192, r = i - s * 192;
        sbias[i] = (s == 0) ? qb[r] : ((s == 2) ? vb[r] : 0.0f);
    }
    stage_A(sm, x + (size_t)blockIdx.x * 24576, t);
    stage_B_async(smb, 0, gwq_hi, gwq_lo, 0, t);

    const int warp_m = warp & 7, warp_n = warp >> 3;

    for (int j = 0; j < 9; ++j) {
        cp_wait0();
        __syncthreads();
        if (j < 8) stage_B_async(smb, (j + 1) & 1, gwq_hi, gwq_lo, (j + 1) * 64, t);

        float acc[4][4];
#pragma unroll
        for (int a = 0; a < 4; ++a)
#pragma unroll
            for (int c = 0; c < 4; ++c) acc[a][c] = 0.f;

        mma_chunk16(smb, j & 1, warp, lane, acc);

        const int jjb = j * 64 + warp_n * 32;
        const int s = jjb / 192, rr = jjb - s * 192, h = rr >> 5;
        {
            int rowA = warp_m * 16 + (lane >> 2);
            int winoff = rowA >> 6, token = rowA & 63;
            float v0[8], v1[8];
#pragma unroll
            for (int tn = 0; tn < 4; ++tn) {
                int jj = jjb + tn * 8 + (lane & 3) * 2;
                float b0 = sbias[jj], b1 = sbias[jj + 1];
                v0[tn * 2]     = acc[tn][0] + b0;
                v0[tn * 2 + 1] = acc[tn][1] + b1;
                v1[tn * 2]     = acc[tn][2] + b0;
                v1[tn * 2 + 1] = acc[tn][3] + b1;
            }
            if (s < 2) {   // q or k: L2-normalize rows (quad holds full 32-d row)
                float ss0 = 0.f, ss1 = 0.f;
#pragma unroll
                for (int e = 0; e < 8; ++e) { ss0 += v0[e] * v0[e]; ss1 += v1[e] * v1[e]; }
                ss0 += __shfl_xor_sync(0xffffffffu, ss0, 1);
                ss0 += __shfl_xor_sync(0xffffffffu, ss0, 2);
                ss1 += __shfl_xor_sync(0xffffffffu, ss1, 1);
                ss1 += __shfl_xor_sync(0xffffffffu, ss1, 2);
                float inv0 = 1.0f / fmaxf(sqrtf(ss0), 1e-12f);
                float inv1 = 1.0f / fmaxf(sqrtf(ss1), 1e-12f);
                if (s == 0) {
                    float sc = expf(fminf(ls[h], 4.6051702f));
                    inv0 *= sc; inv1 *= sc;
                }
#pragma unroll
                for (int e = 0; e < 8; ++e) { v0[e] *= inv0; v1[e] *= inv1; }
            }
            __nv_bfloat16 *dhi, *dlo;
            if (s == 0)      { dhi = g_qh; dlo = g_ql; }
            else if (s == 1) { dhi = g_kh; dlo = g_kl; }
            else             { dhi = g_vh; dlo = g_vl; }
            size_t base = ((((size_t)blockIdx.x * 2 + winoff) * HEADS + h) * 64 + token) * 32;
#pragma unroll
            for (int tn = 0; tn < 4; ++tn) {
                int d = tn * 8 + (lane & 3) * 2;
                float a0 = v0[tn * 2], a1 = v0[tn * 2 + 1];
                float c0 = v1[tn * 2], c1 = v1[tn * 2 + 1];
                __nv_bfloat16 h0 = __float2bfloat16(a0), h1 = __float2bfloat16(a1);
                *(uint32_t*)(dhi + base + d) = pk(h0, h1);
                *(uint32_t*)(dlo + base + d) =
                    pk(__float2bfloat16(a0 - __bfloat162float(h0)),
                       __float2bfloat16(a1 - __bfloat162float(h1)));
                __nv_bfloat16 g0 = __float2bfloat16(c0), g1 = __float2bfloat16(c1);
                *(uint32_t*)(dhi + base + 256 + d) = pk(g0, g1);
                *(uint32_t*)(dlo + base + 256 + d) =
                    pk(__float2bfloat16(c0 - __bfloat162float(g0)),
                       __float2bfloat16(c1 - __bfloat162float(g1)));
            }
        }
        __syncthreads();
    }
}

// ---------------------------------------------------------------------------
// proj GEMM: A = attention output (bf16 hi/lo in gmem) via cp.async. 512 thr.
// ---------------------------------------------------------------------------
__global__ __launch_bounds__(GEMM_THREADS, 1)
void proj_mma_kernel(const float* __restrict__ pb, float* __restrict__ out) {
    extern __shared__ char sm[];
    const uint32_t smb = smem_u32(sm);
    const int t = threadIdx.x, warp = t >> 5, lane = t & 31;

    float* sbias = (float*)(sm + SBIAS);
    for (int i = t; i < 192; i += GEMM_THREADS) sbias[i] = pb[i];
    {
        const char* sh = (const char*)(g_oh + (size_t)blockIdx.x * 24576);
        const char* sl = (const char*)(g_ol + (size_t)blockIdx.x * 24576);
#pragma unroll
        for (int i = t; i < 3072; i += GEMM_THREADS) {
            int row = i / 24, c = (i - row * 24) * 16;
            cp_async16(smb + A_HI + row * ASTRIDE + c, sh + row * 384 + c);
            cp_async16(smb + A_LO + row * ASTRIDE + c, sl + row * 384 + c);
        }
    }
    stage_B_async(smb, 0, gwp_hi, gwp_lo, 0, t);

    const int warp_m = warp & 7, warp_n = warp >> 3;
    float* outg = out + (size_t)blockIdx.x * 24576;

    for (int j = 0; j < 3; ++j) {
        cp_wait0();
        __syncthreads();
        if (j < 2) stage_B_async(smb, (j + 1) & 1, gwp_hi, gwp_lo, (j + 1) * 64, t);

        float acc[4][4];
#pragma unroll
        for (int a = 0; a < 4; ++a)
#pragma unroll
            for (int c = 0; c < 4; ++c) acc[a][c] = 0.f;

        mma_chunk16(smb, j & 1, warp, lane, acc);

        int rowA = warp_m * 16 + (lane >> 2);
#pragma unroll
        for (int tn = 0; tn < 4; ++tn) {
            int jj = j * 64 + warp_n * 32 + tn * 8 + (lane & 3) * 2;
            float b0 = sbias[jj], b1 = sbias[jj + 1];
            *(float2*)(outg + (size_t)rowA * 192 + jj) =
                make_float2(acc[tn][0] + b0, acc[tn][1] + b1);
            *(float2*)(outg + (size_t)(rowA + 8) * 192 + jj) =
                make_float2(acc[tn][2] + b0, acc[tn][3] + b1);
        }
        __syncthreads();
    }
}

// ================= CPB + combined bias/mask table =================
__global__ void cpb_kernel(const float* __restrict__ w1, const float* __restrict__ b1,
                           const float* __restrict__ w2) {
    __shared__ float tbl[225 * 6];
    int t = threadIdx.x;
    if (t < 225) {
        int a = t / 15, bb = t % 15;
        float th = (float)(a - 7) * (8.0f / 7.0f);
        float tw = (float)(bb - 7) * (8.0f / 7.0f);
        th = copysignf(log2f(fabsf(th) + 1.0f) * (1.0f / 3.0f), th);
        tw = copysignf(log2f(fabsf(tw) + 1.0f) * (1.0f / 3.0f), tw);
        float acc[6] = {0.f, 0.f, 0.f, 0.f, 0.f, 0.f};
        for (int j = 0; j < 512; ++j) {
            float hv = fmaf(th, w1[2 * j], fmaf(tw, w1[2 * j + 1], b1[j]));
            hv = fmaxf(hv, 0.0f);
#pragma unroll
            for (int hh = 0; hh < 6; ++hh)
                acc[hh] = fmaf(hv, w2[hh * 512 + j], acc[hh]);
        }
#pragma unroll
        for (int hh = 0; hh < 6; ++hh) tbl[t * 6 + hh] = acc[hh];
    }
    __syncthreads();
    for (int idx = t; idx < HEADS * 4096; idx += blockDim.x) {
        int h = idx >> 12;
        int p = idx & 4095;
        int i = p >> 6, j = p & 63;
        int dh = (i >> 3) - (j >> 3) + 7;
        int dw = (i & 7) - (j & 7) + 7;
        float v = tbl[(dh * 15 + dw) * 6 + h];
        g_bias16[idx] = 16.0f / (1.0f + expf(-v));
    }
}

__global__ void bm_kernel(const float* __restrict__ mask) {
    int w = blockIdx.x / HEADS, h = blockIdx.x % HEADS;
    const float* mw = mask + (size_t)w * 4096;
    const float* bh = g_bias16 + h * 4096;
    float* dst = g_bm + ((size_t)w * HEADS + h) * 4096;
    for (int i = threadIdx.x; i < 4096; i += blockDim.x)
        dst[i] = mw[i] + bh[i];
}

// ================= MMA attention: one CTA per window, 6-head loop ===========
// Phases per head: S (bias folded into acc) -> softmax (writes P bf16 directly)
// -> AV (stores fragments straight to gmem). q/k prefetched for h+1 during
// softmax/AV; v prefetched after AV. 4 syncs/head.
#define QHI_O 0
#define QLO_O 5120
#define KHI_O 10240
#define KLO_O 15360
#define VHI_O 20480
#define VLO_O 25600
#define AT_O  30720          /* fp32 64 x 68 */
#define PHI_O 48128          /* bf16 64 rows x 144 B */
#define PLO_O 57344
#define SM_ATTN 66560

__global__ __launch_bounds__(256)
void attn_mma_kernel() {
    extern __shared__ char sm[];
    const uint32_t smb = smem_u32(sm);
    const int b = blockIdx.x, t = threadIdx.x;
    const int warp = t >> 5, lane = t & 31;
    const int warp_m = warp & 3, warp_n = warp >> 2;     // 4 m16-tiles x 2 n-tiles
    const uint32_t lrow = lane & 15, lcol = (lane >> 4) * 16;

    float* at = (float*)(sm + AT_O);     // 64 x 68

    // preload head-0 tiles (all 6)
    {
        size_t hb = ((size_t)b * HEADS + 0) * 2048;
        const char* srcs[6] = {
            (const char*)(g_qh + hb), (const char*)(g_ql + hb),
            (const char*)(g_kh + hb), (const char*)(g_kl + hb),
            (const char*)(g_vh + hb), (const char*)(g_vl + hb)};
        const uint32_t offs[6] = {QHI_O, QLO_O, KHI_O, KLO_O, VHI_O, VLO_O};
#pragma unroll
        for (int i = t; i < 1536; i += 256) {
            int arr = i >> 8, c = i & 255;
            int row = c >> 2, c16 = (c & 3) * 16;
            cp_async16(smb + offs[arr] + row * 80 + c16, srcs[arr] + row * 64 + c16);
        }
        cp_commit();
    }

    for (int h = 0; h < HEADS; ++h) {
        cp_wait0();
        __syncthreads();

        // ---- phase S: S = qn @ kn^T (3-term); bias+mask folded into epilogue
        {
            const float* bm = g_bm + ((size_t)(b & 63) * HEADS + h) * 4096;
            const int m0 = warp_m * 16 + (lane >> 2);
            float2 bm0[4], bm1[4];
#pragma unroll
            for (int tn = 0; tn < 4; ++tn) {
                int n = warp_n * 32 + tn * 8 + (lane & 3) * 2;
                bm0[tn] = *(const float2*)(bm + m0 * 64 + n);
                bm1[tn] = *(const float2*)(bm + (m0 + 8) * 64 + n);
            }

            float acc[4][4];
#pragma unroll
            for (int a = 0; a < 4; ++a)
#pragma unroll
                for (int c = 0; c < 4; ++c) acc[a][c] = 0.f;

            const uint32_t qa = smb + QHI_O + (warp_m * 16 + lrow) * 80 + lcol;
            const uint32_t ka = smb + KHI_O + (warp_n * 32 + lrow) * 80 + lcol;
#pragma unroll
            for (int ks = 0; ks < 2; ++ks) {
                uint32_t ah[4], al[4], bh[2][4], bl[2][4];
                ldsm4(ah, qa + ks * 32);
                ldsm4(al, qa + (QLO_O - QHI_O) + ks * 32);
#pragma unroll
                for (int nh = 0; nh < 2; ++nh) {
                    ldsm4(bh[nh], ka + nh * 1280 + ks * 32);
                    ldsm4(bl[nh], ka + (KLO_O - KHI_O) + nh * 1280 + ks * 32);
                }
#pragma unroll
                for (int nh = 0; nh < 2; ++nh) {
                    uint32_t b0h[2] = {bh[nh][0], bh[nh][2]};
                    uint32_t b1h[2] = {bh[nh][1], bh[nh][3]};
                    uint32_t b0l[2] = {bl[nh][0], bl[nh][2]};
                    uint32_t b1l[2] = {bl[nh][1], bl[nh][3]};
                    mma16816(acc[nh * 2 + 0], ah, b0h);
                    mma16816(acc[nh * 2 + 0], ah, b0l);
                    mma16816(acc[nh * 2 + 0], al, b0h);
                    mma16816(acc[nh * 2 + 1], ah, b1h);
                    mma16816(acc[nh * 2 + 1], ah, b1l);
                    mma16816(acc[nh * 2 + 1], al, b1h);
                }
            }
#pragma unroll
            for (int tn = 0; tn < 4; ++tn) {
                int n = warp_n * 32 + tn * 8 + (lane & 3) * 2;
                at[m0 * 68 + n]           = acc[tn][0] + bm0[tn].x;
                at[m0 * 68 + n + 1]       = acc[tn][1] + bm0[tn].y;
                at[(m0 + 8) * 68 + n]     = acc[tn][2] + bm1[tn].x;
                at[(m0 + 8) * 68 + n + 1] = acc[tn][3] + bm1[tn].y;
            }
        }
        __syncthreads();

        // prefetch next head's q/k (q,k tiles are dead after S)
        if (h < HEADS - 1) {
            size_t hb = ((size_t)b * HEADS + h + 1) * 2048;
            const char* srcs[4] = {
                (const char*)(g_qh + hb), (const char*)(g_ql + hb),
                (const char*)(g_kh + hb), (const char*)(g_kl + hb)};
            const uint32_t offs[4] = {QHI_O, QLO_O, KHI_O, KLO_O};
#pragma unroll
            for (int i = t; i < 1024; i += 256) {
                int arr = i >> 8, c = i & 255;
                int row = c >> 2, c16 = (c & 3) * 16;
                cp_async16(smb + offs[arr] + row * 80 + c16, srcs[arr] + row * 64 + c16);
            }
            cp_commit();
        }

        // ---- softmax: warp per row, writes P hi/lo bf16 directly
        for (int row = warp; row < 64; row += 8) {
            float a0 = at[row * 68 + lane];
            float a1 = at[row * 68 + 32 + lane];
            float mx = fmaxf(a0, a1);
#pragma unroll
            for (int off = 16; off; off >>= 1)
                mx = fmaxf(mx, __shfl_xor_sync(0xffffffffu, mx, off));
            float e0 = __expf(a0 - mx);
            float e1 = __expf(a1 - mx);
            float ssum = e0 + e1;
#pragma unroll
            for (int off = 16; off; off >>= 1)
                ssum += __shfl_xor_sync(0xffffffffu, ssum, off);
            float inv = 1.0f / ssum;
            float p0 = e0 * inv, p1 = e1 * inv;
            __nv_bfloat16 h0 = __float2bfloat16(p0);
            __nv_bfloat16 h1 = __float2bfloat16(p1);
            *(__nv_bfloat16*)(sm + PHI_O + row * 144 + lane * 2) = h0;
            *(__nv_bfloat16*)(sm + PLO_O + row * 144 + lane * 2) =
                __float2bfloat16(p0 - __bfloat162float(h0));
            *(__nv_bfloat16*)(sm + PHI_O + row * 144 + (32 + lane) * 2) = h1;
            *(__nv_bfloat16*)(sm + PLO_O + row * 144 + (32 + lane) * 2) =
                __float2bfloat16(p1 - __bfloat162float(h1));
        }
        __syncthreads();

        // ---- AV: out = P @ V (3-term), fragments stored straight to gmem
        {
            float av[2][4];
#pragma unroll
            for (int a = 0; a < 2; ++a)
#pragma unroll
                for (int c = 0; c < 4; ++c) av[a][c] = 0.f;

            const uint32_t pa = smb + PHI_O + (warp_m * 16 + lrow) * 144 + lcol;
            const uint32_t va = smb + VHI_O + lrow * 80 + lcol + warp_n * 32;
#pragma unroll
            for (int ks = 0; ks < 4; ++ks) {
                uint32_t aph[4], apl[4], bvh[4], bvl[4];
                ldsm4(aph, pa + ks * 32);
                ldsm4(apl, pa + (PLO_O - PHI_O) + ks * 32);
                ldsm4t(bvh, va + ks * 16 * 80);
                ldsm4t(bvl, va + (VLO_O - VHI_O) + ks * 16 * 80);
                uint32_t b0h[2] = {bvh[0], bvh[1]};
                uint32_t b1h[2] = {bvh[2], bvh[3]};
                uint32_t b0l[2] = {bvl[0], bvl[1]};
                uint32_t b1l[2] = {bvl[2], bvl[3]};
                mma16816(av[0], aph, b0h);
                mma16816(av[0], aph, b0l);
                mma16816(av[0], apl, b0h);
                mma16816(av[1], aph, b1h);
                mma16816(av[1], aph, b1l);
                mma16816(av[1], apl, b1h);
            }
            int m = warp_m * 16 + (lane >> 2);
#pragma unroll
            for (int dn = 0; dn < 2; ++dn) {
                int d = warp_n * 16 + dn * 8 + (lane & 3) * 2;
                size_t o0 = ((size_t)b * 64 + m) * 192 + h * 32 + d;
                size_t o1 = ((size_t)b * 64 + m + 8) * 192 + h * 32 + d;
                float x0 = av[dn][0], x1 = av[dn][1];
                float x2 = av[dn][2], x3 = av[dn][3];
                __nv_bfloat16 h0 = __float2bfloat16(x0), h1 = __float2bfloat16(x1);
                __nv_bfloat16 h2 = __float2bfloat16(x2), h3 = __float2bfloat16(x3);
                *(uint32_t*)(g_oh + o0) = pk(h0, h1);
                *(uint32_t*)(g_ol + o0) =
                    pk(__float2bfloat16(x0 - __bfloat162float(h0)),
                       __float2bfloat16(x1 - __bfloat162float(h1)));
                *(uint32_t*)(g_oh + o1) = pk(h2, h3);
                *(uint32_t*)(g_ol + o1) =
                    pk(__float2bfloat16(x2 - __bfloat162float(h2)),
                       __float2bfloat16(x3 - __bfloat162float(h3)));
            }
        }
        __syncthreads();

        // prefetch next head's v (v tiles are dead after AV)
        if (h < HEADS - 1) {
            size_t hb = ((size_t)b * HEADS + h + 1) * 2048;
            const char* srcs[2] = {(const char*)(g_vh + hb), (const char*)(g_vl + hb)};
            const uint32_t offs[2] = {VHI_O, VLO_O};
#pragma unroll
            for (int i = t; i < 512; i += 256) {
                int arr = i >> 8, c = i & 255;
                int row = c >> 2, c16 = (c & 3) * 16;
                cp_async16(smb + offs[arr] + row * 80 + c16, srcs[arr] + row * 64 + c16);
            }
            cp_commit();
        }
    }
}

// ---------------------------------------------------------------------------
extern "C" void kernel_launch(void* const* d_in, const int* in_sizes, int n_in,
                              void* d_out, int out_size) {
    const float* x    = (const float*)d_in[0];
    const float* mask = (const float*)d_in[1];
    const float* qkvw = (const float*)d_in[2];
    const float* qb   = (const float*)d_in[3];
    const float* vb   = (const float*)d_in[4];
    const float* ls   = (const float*)d_in[5];
    const float* w1   = (const float*)d_in[6];
    const float* b1   = (const float*)d_in[7];
    const float* w2   = (const float*)d_in[8];
    const float* pw   = (const float*)d_in[9];
    const float* pb   = (const float*)d_in[10];
    float* out = (float*)d_out;

    int B = in_sizes[0] / (NTOK * DIM);

    cudaFuncSetAttribute(qkv_mma_kernel,
                         cudaFuncAttributeMaxDynamicSharedMemorySize, SM_DYN);
    cudaFuncSetAttribute(proj_mma_kernel,
                         cudaFuncAttributeMaxDynamicSharedMemorySize, SM_DYN);
    cudaFuncSetAttribute(attn_mma_kernel,
                         cudaFuncAttributeMaxDynamicSharedMemorySize, SM_ATTN);

    prep_w_kernel<<<144, 256>>>(qkvw, pw);
    cpb_kernel<<<1, 256>>>(w1, b1, w2);
    bm_kernel<<<64 * HEADS, 256>>>(mask);
    qkv_mma_kernel<<<B / 2, GEMM_THREADS, SM_DYN>>>(x, qb, vb, ls);
    attn_mma_kernel<<<B, 256, SM_ATTN>>>();
    proj_mma_kernel<<<B / 2, GEMM_THREADS, SM_DYN>>>(pb, out);
}

// round 17
// speedup vs baseline: 1.0265x; 1.0265x over previous
#include <cuda_runtime.h>
#include <cuda_bf16.h>
#include <math.h>
#include <stdint.h>

#define HEADS 6
#define NTOK  64
#define DIM   192
#define MAXB  4096

// ---------------- device scratch ----------------
__device__ float g_bias16[HEADS * NTOK * NTOK];
__device__ float g_bm[64 * HEADS * NTOK * NTOK];   // mask + bias16 combined
// normalized (scale folded) q, k and v, bf16 hi/lo split, [b][h][n][32]
__device__ __align__(16) __nv_bfloat16 g_qh[(size_t)MAXB * HEADS * 2048];
__device__ __align__(16) __nv_bfloat16 g_ql[(size_t)MAXB * HEADS * 2048];
__device__ __align__(16) __nv_bfloat16 g_kh[(size_t)MAXB * HEADS * 2048];
__device__ __align__(16) __nv_bfloat16 g_kl[(size_t)MAXB * HEADS * 2048];
__device__ __align__(16) __nv_bfloat16 g_vh[(size_t)MAXB * HEADS * 2048];
__device__ __align__(16) __nv_bfloat16 g_vl[(size_t)MAXB * HEADS * 2048];
// attention output, bf16 hi/lo, [b][n][192]
__device__ __align__(16) __nv_bfloat16 g_oh[(size_t)MAXB * NTOK * DIM];
__device__ __align__(16) __nv_bfloat16 g_ol[(size_t)MAXB * NTOK * DIM];
// weights bf16 hi/lo
__device__ __align__(16) __nv_bfloat16 gwq_hi[576 * 192];
__device__ __align__(16) __nv_bfloat16 gwq_lo[576 * 192];
__device__ __align__(16) __nv_bfloat16 gwp_hi[192 * 192];
__device__ __align__(16) __nv_bfloat16 gwp_lo[192 * 192];

// ---------------- arch-generic PTX helpers ----------------
__device__ __forceinline__ uint32_t smem_u32(const void* p) {
    uint32_t a;
    asm("{ .reg .u64 t; cvta.to.shared.u64 t, %1; cvt.u32.u64 %0, t; }" : "=r"(a) : "l"(p));
    return a;
}
__device__ __forceinline__ void cp_async16(uint32_t saddr, const void* gptr) {
    asm volatile("cp.async.cg.shared.global [%0], [%1], 16;" :: "r"(saddr), "l"(gptr)
                 : "memory");
}
__device__ __forceinline__ void cp_commit() {
    asm volatile("cp.async.commit_group;" ::: "memory");
}
__device__ __forceinline__ void cp_wait0() {
    asm volatile("cp.async.wait_group 0;" ::: "memory");
}
__device__ __forceinline__ void ldsm4(uint32_t* r, uint32_t addr) {
    asm volatile("ldmatrix.sync.aligned.m8n8.x4.shared.b16 {%0,%1,%2,%3}, [%4];"
                 : "=r"(r[0]), "=r"(r[1]), "=r"(r[2]), "=r"(r[3]) : "r"(addr));
}
__device__ __forceinline__ void ldsm4t(uint32_t* r, uint32_t addr) {
    asm volatile("ldmatrix.sync.aligned.m8n8.x4.trans.shared.b16 {%0,%1,%2,%3}, [%4];"
                 : "=r"(r[0]), "=r"(r[1]), "=r"(r[2]), "=r"(r[3]) : "r"(addr));
}
__device__ __forceinline__ void mma16816(float* c, const uint32_t* a, const uint32_t* b) {
    asm volatile(
        "mma.sync.aligned.m16n8k16.row.col.f32.bf16.bf16.f32 "
        "{%0,%1,%2,%3}, {%4,%5,%6,%7}, {%8,%9}, {%0,%1,%2,%3};"
        : "+f"(c[0]), "+f"(c[1]), "+f"(c[2]), "+f"(c[3])
        : "r"(a[0]), "r"(a[1]), "r"(a[2]), "r"(a[3]), "r"(b[0]), "r"(b[1]));
}
__device__ __forceinline__ uint32_t pk(__nv_bfloat16 a, __nv_bfloat16 b) {
    __nv_bfloat162 t = __halves2bfloat162(a, b);
    return *(uint32_t*)&t;
}

// ================= GEMM common (M=64 per CTA, 2 CTAs/SM) =================
#define ASTRIDE 400
#define A_HI    0
#define A_LO    25600
#define B_HI_O  51200
#define B_LO_O  76800
#define SBIAS   102400
#define SM_DYN  (102400 + 2304)     /* 104704 B -> 2 CTAs/SM */
#define GEMM_THREADS 256

__global__ void prep_w_kernel(const float* __restrict__ qkvw, const float* __restrict__ pw) {
    const int n1 = 576 * 192, n2 = 192 * 192;
    for (int i = blockIdx.x * blockDim.x + threadIdx.x; i < n1 + n2;
         i += gridDim.x * blockDim.x) {
        float v = (i < n1) ? qkvw[i] : pw[i - n1];
        __nv_bfloat16 h = __float2bfloat16(v);
        __nv_bfloat16 l = __float2bfloat16(v - __bfloat162float(h));
        if (i < n1) { gwq_hi[i] = h; gwq_lo[i] = l; }
        else        { gwp_hi[i - n1] = h; gwp_lo[i - n1] = l; }
    }
}

// stage A (fp32 -> bf16 hi/lo), 64 rows x 192 cols
__device__ __forceinline__ void stage_A64(char* sm, const float* __restrict__ A, int t) {
    const float4* src = (const float4*)A;
#pragma unroll 4
    for (int i = t; i < 3072; i += GEMM_THREADS) {
        float4 v = src[i];
        int row = i / 48, c4 = (i - row * 48) * 4;
        __nv_bfloat16 hx = __float2bfloat16(v.x), hy = __float2bfloat16(v.y);
        __nv_bfloat16 hz = __float2bfloat16(v.z), hw = __float2bfloat16(v.w);
        __nv_bfloat16 lx = __float2bfloat16(v.x - __bfloat162float(hx));
        __nv_bfloat16 ly = __float2bfloat16(v.y - __bfloat162float(hy));
        __nv_bfloat16 lz = __float2bfloat16(v.z - __bfloat162float(hz));
        __nv_bfloat16 lw = __float2bfloat16(v.w - __bfloat162float(hw));
        uint32_t off = row * ASTRIDE + c4 * 2;
        *(uint2*)(sm + A_HI + off) = make_uint2(pk(hx, hy), pk(hz, hw));
        *(uint2*)(sm + A_LO + off) = make_uint2(pk(lx, ly), pk(lz, lw));
    }
}

// stage one 64-row B chunk (hi+lo) via cp.async into the single B buffer
__device__ __forceinline__ void stage_B_async(uint32_t smb,
                                              const __nv_bfloat16* __restrict__ Whi,
                                              const __nv_bfloat16* __restrict__ Wlo,
                                              int J, int t) {
    uint32_t bh = smb + B_HI_O, bl = smb + B_LO_O;
#pragma unroll
    for (int i = t; i < 1536; i += GEMM_THREADS) {
        int n = i / 24, c = (i - n * 24) * 16;
        uint32_t so = n * ASTRIDE + c;
        cp_async16(bh + so, (const char*)(Whi + (size_t)(J + n) * 192) + c);
        cp_async16(bl + so, (const char*)(Wlo + (size_t)(J + n) * 192) + c);
    }
    cp_commit();
}

// Warp tile 16(M) x 32(N); 8 warps: warp_m = warp&3 (4 m16), warp_n = warp>>2 (2 n32).
__device__ __forceinline__ void mma_chunk64(uint32_t smb, int warp, int lane,
                                            float acc[4][4]) {
    const int warp_m = warp & 3, warp_n = warp >> 2;
    const uint32_t lrow = lane & 15;
    const uint32_t lcol = (lane >> 4) * 16;
    const uint32_t a_hi = smb + A_HI + (warp_m * 16 + lrow) * ASTRIDE + lcol;
    const uint32_t a_lo = a_hi + (A_LO - A_HI);
    const uint32_t b_hi = smb + B_HI_O + (warp_n * 32 + lrow) * ASTRIDE + lcol;
    const uint32_t b_lo = b_hi + (B_LO_O - B_HI_O);

#pragma unroll
    for (int ks = 0; ks < 12; ++ks) {
        uint32_t ah[4], al[4], bh[2][4], bl[2][4];
        ldsm4(ah, a_hi + ks * 32);
        ldsm4(al, a_lo + ks * 32);
#pragma unroll
        for (int nh = 0; nh < 2; ++nh) {
            ldsm4(bh[nh], b_hi + nh * 16 * ASTRIDE + ks * 32);
            ldsm4(bl[nh], b_lo + nh * 16 * ASTRIDE + ks * 32);
        }
#pragma unroll
        for (int nh = 0; nh < 2; ++nh) {
            uint32_t b0h[2] = {bh[nh][0], bh[nh][2]};
            uint32_t b1h[2] = {bh[nh][1], bh[nh][3]};
            uint32_t b0l[2] = {bl[nh][0], bl[nh][2]};
            uint32_t b1l[2] = {bl[nh][1], bl[nh][3]};
            mma16816(acc[nh * 2 + 0], ah, b0h);
            mma16816(acc[nh * 2 + 0], ah, b0l);
            mma16816(acc[nh * 2 + 0], al, b0h);
            mma16816(acc[nh * 2 + 1], ah, b1h);
            mma16816(acc[nh * 2 + 1], ah, b1l);
            mma16816(acc[nh * 2 + 1], al, b1h);
        }
    }
}

// ---------------------------------------------------------------------------
// qkv GEMM + fused normalize/scale/bf16-split epilogue. 1 window/CTA, 2 CTA/SM.
// ---------------------------------------------------------------------------
__global__ __launch_bounds__(GEMM_THREADS, 2)
void qkv_mma_kernel(const float* __restrict__ x, const float* __restrict__ qb,
                    const float* __restrict__ vb, const float* __restrict__ ls) {
    extern __shared__ char sm[];
    const uint32_t smb = smem_u32(sm);
    const int t = threadIdx.x, warp = t >> 5, lane = t & 31;
    const int b = blockIdx.x;

    float* sbias = (float*)(sm + SBIAS);
    for (int i = t; i < 576; i += GEMM_THREADS) {
        int s = i / 192, r = i - s * 192;
        sbias[i] = (s == 0) ? qb[r] : ((s == 2) ? vb[r] : 0.0f);
    }
    stage_B_async(smb, gwq_hi, gwq_lo, 0, t);
    stage_A64(sm, x + (size_t)b * 12288, t);

    const int warp_m = warp & 3, warp_n = warp >> 2;

    for (int j = 0; j < 9; ++j) {
        cp_wait0();
        __syncthreads();

        float acc[4][4];
#pragma unroll
        for (int a = 0; a < 4; ++a)
#pragma unroll
            for (int c = 0; c < 4; ++c) acc[a][c] = 0.f;

        mma_chunk64(smb, warp, lane, acc);
        __syncthreads();                       // all warps done reading B
        if (j < 8) stage_B_async(smb, gwq_hi, gwq_lo, (j + 1) * 64, t);

        const int jjb = j * 64 + warp_n * 32;
        const int s = jjb / 192, rr = jjb - s * 192, h = rr >> 5;
        {
            int token = warp_m * 16 + (lane >> 2);
            float v0[8], v1[8];
#pragma unroll
            for (int tn = 0; tn < 4; ++tn) {
                int jj = jjb + tn * 8 + (lane & 3) * 2;
                float b0 = sbias[jj], b1 = sbias[jj + 1];
                v0[tn * 2]     = acc[tn][0] + b0;
                v0[tn * 2 + 1] = acc[tn][1] + b1;
                v1[tn * 2]     = acc[tn][2] + b0;
                v1[tn * 2 + 1] = acc[tn][3] + b1;
            }
            if (s < 2) {   // q or k: L2-normalize rows (quad holds full 32-d row)
                float ss0 = 0.f, ss1 = 0.f;
#pragma unroll
                for (int e = 0; e < 8; ++e) { ss0 += v0[e] * v0[e]; ss1 += v1[e] * v1[e]; }
                ss0 += __shfl_xor_sync(0xffffffffu, ss0, 1);
                ss0 += __shfl_xor_sync(0xffffffffu, ss0, 2);
                ss1 += __shfl_xor_sync(0xffffffffu, ss1, 1);
                ss1 += __shfl_xor_sync(0xffffffffu, ss1, 2);
                float inv0 = 1.0f / fmaxf(sqrtf(ss0), 1e-12f);
                float inv1 = 1.0f / fmaxf(sqrtf(ss1), 1e-12f);
                if (s == 0) {
                    float sc = expf(fminf(ls[h], 4.6051702f));
                    inv0 *= sc; inv1 *= sc;
                }
#pragma unroll
                for (int e = 0; e < 8; ++e) { v0[e] *= inv0; v1[e] *= inv1; }
            }
            __nv_bfloat16 *dhi, *dlo;
            if (s == 0)      { dhi = g_qh; dlo = g_ql; }
            else if (s == 1) { dhi = g_kh; dlo = g_kl; }
            else             { dhi = g_vh; dlo = g_vl; }
            size_t base = (((size_t)b * HEADS + h) * 64 + token) * 32;
#pragma unroll
            for (int tn = 0; tn < 4; ++tn) {
                int d = tn * 8 + (lane & 3) * 2;
                float a0 = v0[tn * 2], a1 = v0[tn * 2 + 1];
                float c0 = v1[tn * 2], c1 = v1[tn * 2 + 1];
                __nv_bfloat16 h0 = __float2bfloat16(a0), h1 = __float2bfloat16(a1);
                *(uint32_t*)(dhi + base + d) = pk(h0, h1);
                *(uint32_t*)(dlo + base + d) =
                    pk(__float2bfloat16(a0 - __bfloat162float(h0)),
                       __float2bfloat16(a1 - __bfloat162float(h1)));
                __nv_bfloat16 g0 = __float2bfloat16(c0), g1 = __float2bfloat16(c1);
                *(uint32_t*)(dhi + base + 256 + d) = pk(g0, g1);
                *(uint32_t*)(dlo + base + 256 + d) =
                    pk(__float2bfloat16(c0 - __bfloat162float(g0)),
                       __float2bfloat16(c1 - __bfloat162float(g1)));
            }
        }
    }
}

// ---------------------------------------------------------------------------
// proj GEMM: A = attention output (bf16 hi/lo in gmem) via cp.async.
// 1 window/CTA, 2 CTAs/SM, 3 chunks.
// ---------------------------------------------------------------------------
__global__ __launch_bounds__(GEMM_THREADS, 2)
void proj_mma_kernel(const float* __restrict__ pb, float* __restrict__ out) {
    extern __shared__ char sm[];
    const uint32_t smb = smem_u32(sm);
    const int t = threadIdx.x, warp = t >> 5, lane = t & 31;
    const int b = blockIdx.x;

    float* sbias = (float*)(sm + SBIAS);
    for (int i = t; i < 192; i += GEMM_THREADS) sbias[i] = pb[i];
    stage_B_async(smb, gwp_hi, gwp_lo, 0, t);
    {
        const char* sh = (const char*)(g_oh + (size_t)b * 12288);
        const char* sl = (const char*)(g_ol + (size_t)b * 12288);
#pragma unroll
        for (int i = t; i < 1536; i += GEMM_THREADS) {
            int row = i / 24, c = (i - row * 24) * 16;
            cp_async16(smb + A_HI + row * ASTRIDE + c, sh + row * 384 + c);
            cp_async16(smb + A_LO + row * ASTRIDE + c, sl + row * 384 + c);
        }
        cp_commit();
    }

    const int warp_m = warp & 3, warp_n = warp >> 2;
    float* outg = out + (size_t)b * 12288;

    for (int j = 0; j < 3; ++j) {
        cp_wait0();
        __syncthreads();

        float acc[4][4];
#pragma unroll
        for (int a = 0; a < 4; ++a)
#pragma unroll
            for (int c = 0; c < 4; ++c) acc[a][c] = 0.f;

        mma_chunk64(smb, warp, lane, acc);
        __syncthreads();
        if (j < 2) stage_B_async(smb, gwp_hi, gwp_lo, (j + 1) * 64, t);

        int rowA = warp_m * 16 + (lane >> 2);
#pragma unroll
        for (int tn = 0; tn < 4; ++tn) {
            int jj = j * 64 + warp_n * 32 + tn * 8 + (lane & 3) * 2;
            float b0 = sbias[jj], b1 = sbias[jj + 1];
            *(float2*)(outg + (size_t)rowA * 192 + jj) =
                make_float2(acc[tn][0] + b0, acc[tn][1] + b1);
            *(float2*)(outg + (size_t)(rowA + 8) * 192 + jj) =
                make_float2(acc[tn][2] + b0, acc[tn][3] + b1);
        }
    }
}

// ================= CPB + combined bias/mask table =================
__global__ void cpb_kernel(const float* __restrict__ w1, const float* __restrict__ b1,
                           const float* __restrict__ w2) {
    __shared__ float tbl[225 * 6];
    int t = threadIdx.x;
    if (t < 225) {
        int a = t / 15, bb = t % 15;
        float th = (float)(a - 7) * (8.0f / 7.0f);
        float tw = (float)(bb - 7) * (8.0f / 7.0f);
        th = copysignf(log2f(fabsf(th) + 1.0f) * (1.0f / 3.0f), th);
        tw = copysignf(log2f(fabsf(tw) + 1.0f) * (1.0f / 3.0f), tw);
        float acc[6] = {0.f, 0.f, 0.f, 0.f, 0.f, 0.f};
        for (int j = 0; j < 512; ++j) {
            float hv = fmaf(th, w1[2 * j], fmaf(tw, w1[2 * j + 1], b1[j]));
            hv = fmaxf(hv, 0.0f);
#pragma unroll
            for (int hh = 0; hh < 6; ++hh)
                acc[hh] = fmaf(hv, w2[hh * 512 + j], acc[hh]);
        }
#pragma unroll
        for (int hh = 0; hh < 6; ++hh) tbl[t * 6 + hh] = acc[hh];
    }
    __syncthreads();
    for (int idx = t; idx < HEADS * 4096; idx += blockDim.x) {
        int h = idx >> 12;
        int p = idx & 4095;
        int i = p >> 6, j = p & 63;
        int dh = (i >> 3) - (j >> 3) + 7;
        int dw = (i & 7) - (j & 7) + 7;
        float v = tbl[(dh * 15 + dw) * 6 + h];
        g_bias16[idx] = 16.0f / (1.0f + expf(-v));
    }
}

__global__ void bm_kernel(const float* __restrict__ mask) {
    int w = blockIdx.x / HEADS, h = blockIdx.x % HEADS;
    const float* mw = mask + (size_t)w * 4096;
    const float* bh = g_bias16 + h * 4096;
    float* dst = g_bm + ((size_t)w * HEADS + h) * 4096;
    for (int i = threadIdx.x; i < 4096; i += blockDim.x)
        dst[i] = mw[i] + bh[i];
}

// ================= MMA attention: one CTA per window, 6-head loop ===========
#define QHI_O 0
#define QLO_O 5120
#define KHI_O 10240
#define KLO_O 15360
#define VHI_O 20480
#define VLO_O 25600
#define AT_O  30720          /* fp32 64 x 68 */
#define PHI_O 48128          /* bf16 64 rows x 144 B */
#define PLO_O 57344
#define SM_ATTN 66560

__global__ __launch_bounds__(256)
void attn_mma_kernel() {
    extern __shared__ char sm[];
    const uint32_t smb = smem_u32(sm);
    const int b = blockIdx.x, t = threadIdx.x;
    const int warp = t >> 5, lane = t & 31;
    const int warp_m = warp & 3, warp_n = warp >> 2;     // 4 m16-tiles x 2 n-tiles
    const uint32_t lrow = lane & 15, lcol = (lane >> 4) * 16;

    float* at = (float*)(sm + AT_O);     // 64 x 68

    // preload head-0 tiles (all 6)
    {
        size_t hb = ((size_t)b * HEADS + 0) * 2048;
        const char* srcs[6] = {
            (const char*)(g_qh + hb), (const char*)(g_ql + hb),
            (const char*)(g_kh + hb), (const char*)(g_kl + hb),
            (const char*)(g_vh + hb), (const char*)(g_vl + hb)};
        const uint32_t offs[6] = {QHI_O, QLO_O, KHI_O, KLO_O, VHI_O, VLO_O};
#pragma unroll
        for (int i = t; i < 1536; i += 256) {
            int arr = i >> 8, c = i & 255;
            int row = c >> 2, c16 = (c & 3) * 16;
            cp_async16(smb + offs[arr] + row * 80 + c16, srcs[arr] + row * 64 + c16);
        }
        cp_commit();
    }

    for (int h = 0; h < HEADS; ++h) {
        cp_wait0();
        __syncthreads();

        // ---- phase S: S = qn @ kn^T (3-term); bias+mask folded into epilogue
        {
            const float* bm = g_bm + ((size_t)(b & 63) * HEADS + h) * 4096;
            const int m0 = warp_m * 16 + (lane >> 2);
            float2 bm0[4], bm1[4];
#pragma unroll
            for (int tn = 0; tn < 4; ++tn) {
                int n = warp_n * 32 + tn * 8 + (lane & 3) * 2;
                bm0[tn] = *(const float2*)(bm + m0 * 64 + n);
                bm1[tn] = *(const float2*)(bm + (m0 + 8) * 64 + n);
            }

            float acc[4][4];
#pragma unroll
            for (int a = 0; a < 4; ++a)
#pragma unroll
                for (int c = 0; c < 4; ++c) acc[a][c] = 0.f;

            const uint32_t qa = smb + QHI_O + (warp_m * 16 + lrow) * 80 + lcol;
            const uint32_t ka = smb + KHI_O + (warp_n * 32 + lrow) * 80 + lcol;
#pragma unroll
            for (int ks = 0; ks < 2; ++ks) {
                uint32_t ah[4], al[4], bh[2][4], bl[2][4];
                ldsm4(ah, qa + ks * 32);
                ldsm4(al, qa + (QLO_O - QHI_O) + ks * 32);
#pragma unroll
                for (int nh = 0; nh < 2; ++nh) {
                    ldsm4(bh[nh], ka + nh * 1280 + ks * 32);
                    ldsm4(bl[nh], ka + (KLO_O - KHI_O) + nh * 1280 + ks * 32);
                }
#pragma unroll
                for (int nh = 0; nh < 2; ++nh) {
                    uint32_t b0h[2] = {bh[nh][0], bh[nh][2]};
                    uint32_t b1h[2] = {bh[nh][1], bh[nh][3]};
                    uint32_t b0l[2] = {bl[nh][0], bl[nh][2]};
                    uint32_t b1l[2] = {bl[nh][1], bl[nh][3]};
                    mma16816(acc[nh * 2 + 0], ah, b0h);
                    mma16816(acc[nh * 2 + 0], ah, b0l);
                    mma16816(acc[nh * 2 + 0], al, b0h);
                    mma16816(acc[nh * 2 + 1], ah, b1h);
                    mma16816(acc[nh * 2 + 1], ah, b1l);
                    mma16816(acc[nh * 2 + 1], al, b1h);
                }
            }
#pragma unroll
            for (int tn = 0; tn < 4; ++tn) {
                int n = warp_n * 32 + tn * 8 + (lane & 3) * 2;
                at[m0 * 68 + n]           = acc[tn][0] + bm0[tn].x;
                at[m0 * 68 + n + 1]       = acc[tn][1] + bm0[tn].y;
                at[(m0 + 8) * 68 + n]     = acc[tn][2] + bm1[tn].x;
                at[(m0 + 8) * 68 + n + 1] = acc[tn][3] + bm1[tn].y;
            }
        }
        __syncthreads();

        // prefetch next head's q/k (q,k tiles are dead after S)
        if (h < HEADS - 1) {
            size_t hb = ((size_t)b * HEADS + h + 1) * 2048;
            const char* srcs[4] = {
                (const char*)(g_qh + hb), (const char*)(g_ql + hb),
                (const char*)(g_kh + hb), (const char*)(g_kl + hb)};
            const uint32_t offs[4] = {QHI_O, QLO_O, KHI_O, KLO_O};
#pragma unroll
            for (int i = t; i < 1024; i += 256) {
                int arr = i >> 8, c = i & 255;
                int row = c >> 2, c16 = (c & 3) * 16;
                cp_async16(smb + offs[arr] + row * 80 + c16, srcs[arr] + row * 64 + c16);
            }
            cp_commit();
        }

        // ---- softmax: warp per row, writes P hi/lo bf16 directly
        for (int row = warp; row < 64; row += 8) {
            float a0 = at[row * 68 + lane];
            float a1 = at[row * 68 + 32 + lane];
            float mx = fmaxf(a0, a1);
#pragma unroll
            for (int off = 16; off; off >>= 1)
                mx = fmaxf(mx, __shfl_xor_sync(0xffffffffu, mx, off));
            float e0 = __expf(a0 - mx);
            float e1 = __expf(a1 - mx);
            float ssum = e0 + e1;
#pragma unroll
            for (int off = 16; off; off >>= 1)
                ssum += __shfl_xor_sync(0xffffffffu, ssum, off);
            float inv = 1.0f / ssum;
            float p0 = e0 * inv, p1 = e1 * inv;
            __nv_bfloat16 h0 = __float2bfloat16(p0);
            __nv_bfloat16 h1 = __float2bfloat16(p1);
            *(__nv_bfloat16*)(sm + PHI_O + row * 144 + lane * 2) = h0;
            *(__nv_bfloat16*)(sm + PLO_O + row * 144 + lane * 2) =
                __float2bfloat16(p0 - __bfloat162float(h0));
            *(__nv_bfloat16*)(sm + PHI_O + row * 144 + (32 + lane) * 2) = h1;
            *(__nv_bfloat16*)(sm + PLO_O + row * 144 + (32 + lane) * 2) =
                __float2bfloat16(p1 - __bfloat162float(h1));
        }
        __syncthreads();

        // ---- AV: out = P @ V (3-term), fragments stored straight to gmem
        {
            float av[2][4];
#pragma unroll
            for (int a = 0; a < 2; ++a)
#pragma unroll
                for (int c = 0; c < 4; ++c) av[a][c] = 0.f;

            const uint32_t pa = smb + PHI_O + (warp_m * 16 + lrow) * 144 + lcol;
            const uint32_t va = smb + VHI_O + lrow * 80 + lcol + warp_n * 32;
#pragma unroll
            for (int ks = 0; ks < 4; ++ks) {
                uint32_t aph[4], apl[4], bvh[4], bvl[4];
                ldsm4(aph, pa + ks * 32);
                ldsm4(apl, pa + (PLO_O - PHI_O) + ks * 32);
                ldsm4t(bvh, va + ks * 16 * 80);
                ldsm4t(bvl, va + (VLO_O - VHI_O) + ks * 16 * 80);
                uint32_t b0h[2] = {bvh[0], bvh[1]};
                uint32_t b1h[2] = {bvh[2], bvh[3]};
                uint32_t b0l[2] = {bvl[0], bvl[1]};
                uint32_t b1l[2] = {bvl[2], bvl[3]};
                mma16816(av[0], aph, b0h);
                mma16816(av[0], aph, b0l);
                mma16816(av[0], apl, b0h);
                mma16816(av[1], aph, b1h);
                mma16816(av[1], aph, b1l);
                mma16816(av[1], apl, b1h);
            }
            int m = warp_m * 16 + (lane >> 2);
#pragma unroll
            for (int dn = 0; dn < 2; ++dn) {
                int d = warp_n * 16 + dn * 8 + (lane & 3) * 2;
                size_t o0 = ((size_t)b * 64 + m) * 192 + h * 32 + d;
                size_t o1 = ((size_t)b * 64 + m + 8) * 192 + h * 32 + d;
                float x0 = av[dn][0], x1 = av[dn][1];
                float x2 = av[dn][2], x3 = av[dn][3];
                __nv_bfloat16 h0 = __float2bfloat16(x0), h1 = __float2bfloat16(x1);
                __nv_bfloat16 h2 = __float2bfloat16(x2), h3 = __float2bfloat16(x3);
                *(uint32_t*)(g_oh + o0) = pk(h0, h1);
                *(uint32_t*)(g_ol + o0) =
                    pk(__float2bfloat16(x0 - __bfloat162float(h0)),
                       __float2bfloat16(x1 - __bfloat162float(h1)));
                *(uint32_t*)(g_oh + o1) = pk(h2, h3);
                *(uint32_t*)(g_ol + o1) =
                    pk(__float2bfloat16(x2 - __bfloat162float(h2)),
                       __float2bfloat16(x3 - __bfloat162float(h3)));
            }
        }
        __syncthreads();

        // prefetch next head's v (v tiles are dead after AV)
        if (h < HEADS - 1) {
            size_t hb = ((size_t)b * HEADS + h + 1) * 2048;
            const char* srcs[2] = {(const char*)(g_vh + hb), (const char*)(g_vl + hb)};
            const uint32_t offs[2] = {VHI_O, VLO_O};
#pragma unroll
            for (int i = t; i < 512; i += 256) {
                int arr = i >> 8, c = i & 255;
                int row = c >> 2, c16 = (c & 3) * 16;
                cp_async16(smb + offs[arr] + row * 80 + c16, srcs[arr] + row * 64 + c16);
            }
            cp_commit();
        }
    }
}

// ---------------------------------------------------------------------------
extern "C" void kernel_launch(void* const* d_in, const int* in_sizes, int n_in,
                              void* d_out, int out_size) {
    const float* x    = (const float*)d_in[0];
    const float* mask = (const float*)d_in[1];
    const float* qkvw = (const float*)d_in[2];
    const float* qb   = (const float*)d_in[3];
    const float* vb   = (const float*)d_in[4];
    const float* ls   = (const float*)d_in[5];
    const float* w1   = (const float*)d_in[6];
    const float* b1   = (const float*)d_in[7];
    const float* w2   = (const float*)d_in[8];
    const float* pw   = (const float*)d_in[9];
    const float* pb   = (const float*)d_in[10];
    float* out = (float*)d_out;

    int B = in_sizes[0] / (NTOK * DIM);

    cudaFuncSetAttribute(qkv_mma_kernel,
                         cudaFuncAttributeMaxDynamicSharedMemorySize, SM_DYN);
    cudaFuncSetAttribute(proj_mma_kernel,
                         cudaFuncAttributeMaxDynamicSharedMemorySize, SM_DYN);
    cudaFuncSetAttribute(attn_mma_kernel,
                         cudaFuncAttributeMaxDynamicSharedMemorySize, SM_ATTN);

    prep_w_kernel<<<144, 256>>>(qkvw, pw);
    cpb_kernel<<<1, 256>>>(w1, b1, w2);
    bm_kernel<<<64 * HEADS, 256>>>(mask);
    qkv_mma_kernel<<<B, GEMM_THREADS, SM_DYN>>>(x, qb, vb, ls);
    attn_mma_kernel<<<B, 256, SM_ATTN>>>();
    proj_mma_kernel<<<B, GEMM_THREADS, SM_DYN>>>(pb, out);
}